// round 3
// baseline (speedup 1.0000x reference)
#include <cuda_runtime.h>
#include <cuda_bf16.h>
#include <math.h>

#define Mm 64
#define Nn 16
#define Dd 300
#define Ff 768
#define VOCAB 100000
#define SURF_L 4
#define CTX_L 50
#define DOC_L 100
#define BODY_L 200
#define HD 60   // head dim
#define NH 5    // heads

// ---------------- scratch (__device__ globals, no allocation) ----------------
__device__ float g_Wt_ms[2 * Dd * Ff];      // [k][d][f]
__device__ float g_Wt_mc[5 * Dd * Ff];      // [k][d][f]
__device__ float g_ms[Mm * Ff];
__device__ float g_mc[Mm * Ff];
__device__ float g_comb[Nn * 600];          // [n][dir*300 + h*60 + j]
__device__ float g_attscore[Nn];
__device__ float g_local[Mm * Nn];
__device__ float g_tn[Nn];
__device__ float g_cosdt[Nn];

// safe id fetch: clamp into valid vocab range so a bad index can never fault
__device__ __forceinline__ int safe_id(const int* p, int i) {
    int v = p[i];
    return v < 0 ? 0 : (v >= VOCAB ? VOCAB - 1 : v);
}

// ---------------- helpers ----------------
__device__ __forceinline__ float warp_sum(float v) {
#pragma unroll
    for (int o = 16; o; o >>= 1) v += __shfl_xor_sync(0xFFFFFFFFu, v, o);
    return v;
}
__device__ __forceinline__ float warp_max(float v) {
#pragma unroll
    for (int o = 16; o; o >>= 1) v = fmaxf(v, __shfl_xor_sync(0xFFFFFFFFu, v, o));
    return v;
}
__device__ __forceinline__ float r16_sum(float v) {
#pragma unroll
    for (int o = 8; o; o >>= 1) v += __shfl_xor_sync(0xFFFFu, v, o, 16);
    return v;
}
__device__ __forceinline__ float r16_max(float v) {
#pragma unroll
    for (int o = 8; o; o >>= 1) v = fmaxf(v, __shfl_xor_sync(0xFFFFu, v, o, 16));
    return v;
}
__device__ __forceinline__ float r16_min(float v) {
#pragma unroll
    for (int o = 8; o; o >>= 1) v = fminf(v, __shfl_xor_sync(0xFFFFu, v, o, 16));
    return v;
}

// ---------------- weight transpose: W[f][d][k] -> Wt[k][d][f] ----------------
template <int K, int WHICH>
__global__ void transpose_w_kernel(const float* __restrict__ W) {
    float* Wt = WHICH ? g_Wt_mc : g_Wt_ms;
    int idx = blockIdx.x * blockDim.x + threadIdx.x;
    const int total = K * Dd * Ff;
    if (idx < total) {
        int f = idx % Ff;
        int rest = idx / Ff;
        int d = rest % Dd;
        int k = rest / Dd;
        Wt[idx] = W[(size_t)f * Dd * K + d * K + k];
    }
}

// ---------------- conv1d(valid) + relu + avgpool ----------------
// out[m][f] = (1/T) * sum_t relu( b[f] + sum_{k,d} X[m][t+k][d] * W[f][d][k] )
template <int L, int K, int T, int TC, int FPT, int WHICH>
__launch_bounds__(128)
__global__ void conv_kernel(const int* __restrict__ ids,
                            const float* __restrict__ emb,
                            const float* __restrict__ bias) {
    const float* Wt = WHICH ? g_Wt_mc : g_Wt_ms;
    float* out = WHICH ? g_mc : g_ms;
    const int m = blockIdx.x;
    const int bd = blockDim.x;
    extern __shared__ float Xs[];  // L*Dd
    for (int i = threadIdx.x; i < L * Dd; i += bd) {
        int l = i / Dd, d = i - l * Dd;
        Xs[i] = emb[(size_t)safe_id(ids, m * L + l) * Dd + d];
    }
    __syncthreads();
    const int f0 = blockIdx.y * (bd * FPT) + threadIdx.x;

    float acc[FPT];
    float bia[FPT];
#pragma unroll
    for (int fp = 0; fp < FPT; fp++) { acc[fp] = 0.f; bia[fp] = bias[f0 + fp * bd]; }

    for (int tc = 0; tc < T; tc += TC) {
        float y[FPT][TC];
#pragma unroll
        for (int fp = 0; fp < FPT; fp++)
#pragma unroll
            for (int t = 0; t < TC; t++) y[fp][t] = 0.f;

#pragma unroll
        for (int k = 0; k < K; k++) {
            const float* __restrict__ wp = Wt + (size_t)k * Dd * Ff + f0;
            const float* __restrict__ xp = Xs + (tc + k) * Dd;
            for (int d = 0; d < Dd; d++) {
                float w[FPT];
#pragma unroll
                for (int fp = 0; fp < FPT; fp++) w[fp] = wp[d * Ff + fp * bd];
#pragma unroll
                for (int t = 0; t < TC; t++) {
                    float xv = xp[t * Dd + d];
#pragma unroll
                    for (int fp = 0; fp < FPT; fp++) y[fp][t] = fmaf(xv, w[fp], y[fp][t]);
                }
            }
        }
#pragma unroll
        for (int t = 0; t < TC; t++) {
            if (tc + t < T) {
#pragma unroll
                for (int fp = 0; fp < FPT; fp++)
                    acc[fp] += fmaxf(y[fp][t] + bia[fp], 0.f);
            }
        }
    }
#pragma unroll
    for (int fp = 0; fp < FPT; fp++)
        out[m * Ff + f0 + fp * bd] = acc[fp] * (1.0f / T);
}

// ---------------- cross attention: per (n, head, dir), max over query ----------------
// dir 0: q = doc(100), k=v = body[n](200)  -> comb[n][0:300]
// dir 1: q = body[n](200), k=v = doc(100)  -> comb[n][300:600]
__global__ void attn_kernel(const int* __restrict__ doc_ids,
                            const int* __restrict__ body_ids,
                            const float* __restrict__ emb) {
    const int n = blockIdx.x, h = blockIdx.y, dir = blockIdx.z;
    const int Lq = dir == 0 ? DOC_L : BODY_L;
    const int Lk = dir == 0 ? BODY_L : DOC_L;
    extern __shared__ float sh[];
    float* qs = sh;               // Lq*HD
    float* ks = qs + Lq * HD;     // Lk*HD
    float* S = ks + Lk * HD;      // Lq*Lk
    __shared__ float red[60 * 4];

    const int tid = threadIdx.x;  // 256
    const int* qids = dir == 0 ? doc_ids : body_ids + n * BODY_L;
    const int* kids = dir == 0 ? body_ids + n * BODY_L : doc_ids;

    for (int i = tid; i < Lq * HD; i += 256) {
        int l = i / HD, j = i - l * HD;
        qs[i] = emb[(size_t)safe_id(qids, l) * Dd + h * HD + j];
    }
    for (int i = tid; i < Lk * HD; i += 256) {
        int l = i / HD, j = i - l * HD;
        ks[i] = emb[(size_t)safe_id(kids, l) * Dd + h * HD + j];
    }
    __syncthreads();

    const float scale = rsqrtf((float)HD);
    for (int idx = tid; idx < Lq * Lk; idx += 256) {
        int q = idx / Lk, k = idx - q * Lk;
        const float* qp = qs + q * HD;
        const float* kp = ks + k * HD;
        float s = 0.f;
#pragma unroll
        for (int j = 0; j < HD; j++) s = fmaf(qp[j], kp[j], s);
        S[idx] = s * scale;
    }
    __syncthreads();

    // row softmax: one warp per row
    const int wid = tid >> 5, lane = tid & 31;
    for (int q = wid; q < Lq; q += 8) {
        float* row = S + q * Lk;
        float mx = -1e30f;
        for (int k = lane; k < Lk; k += 32) mx = fmaxf(mx, row[k]);
        mx = warp_max(mx);
        float sum = 0.f;
        for (int k = lane; k < Lk; k += 32) {
            float e = expf(row[k] - mx);
            row[k] = e;
            sum += e;
        }
        sum = warp_sum(sum);
        float inv = 1.f / sum;
        for (int k = lane; k < Lk; k += 32) row[k] *= inv;
    }
    __syncthreads();

    // out[q][j] = sum_k P[q][k] * v[k][j]; then max over q (split into 4 q-groups)
    const int qper = Lq / 4;
    if (tid < 240) {
        int g = tid / 60, j = tid - g * 60;
        float mx = -1e30f;
        for (int q = g * qper; q < (g + 1) * qper; q++) {
            const float* row = S + q * Lk;
            float o = 0.f;
            for (int k = 0; k < Lk; k++) o = fmaf(row[k], ks[k * HD + j], o);
            mx = fmaxf(mx, o);
        }
        red[j * 4 + g] = mx;
    }
    __syncthreads();
    if (tid < 60) {
        float mx = fmaxf(fmaxf(red[tid * 4], red[tid * 4 + 1]),
                         fmaxf(red[tid * 4 + 2], red[tid * 4 + 3]));
        g_comb[n * 600 + dir * 300 + h * HD + tid] = mx;
    }
}

// ---------------- attention MLP: sigmoid(relu(comb@W1+b1)@W2+b2) ----------------
__global__ void attmlp_kernel(const float* __restrict__ W1,
                              const float* __restrict__ b1,
                              const float* __restrict__ W2,
                              const float* __restrict__ b2) {
    const int n = blockIdx.x;
    __shared__ float cb[600];
    __shared__ float partial[10];
    const int tid = threadIdx.x;  // 320
    for (int i = tid; i < 600; i += 320) cb[i] = g_comb[n * 600 + i];
    __syncthreads();
    float v = 0.f;
    if (tid < 300) {
        float a = b1[tid];
        for (int i = 0; i < 600; i++) a = fmaf(cb[i], W1[i * 300 + tid], a);
        a = fmaxf(a, 0.f);
        v = a * W2[tid];
    }
    v = warp_sum(v);
    if ((tid & 31) == 0) partial[tid >> 5] = v;
    __syncthreads();
    if (tid == 0) {
        float s = 0.f;
        for (int w = 0; w < 10; w++) s += partial[w];
        s += b2[0];
        g_attscore[n] = 1.f / (1.f + expf(-s));
    }
}

// ---------------- LocalCtxAttRanker ----------------
__global__ void localctx_kernel(const int* __restrict__ cand_ids,
                                const int* __restrict__ ctx_ids,
                                const float* __restrict__ emb) {
    const int m = blockIdx.x;
    extern __shared__ float sh[];
    float* cs = sh;                 // 16*300
    float* xs = cs + Nn * Dd;       // 50*300
    float* tok = xs + CTX_L * Dd;   // 16*50
    float* p = tok + Nn * CTX_L;    // 50
    float* ctxv = p + CTX_L;        // 300
    const int tid = threadIdx.x;    // 256

    for (int i = tid; i < Nn * Dd; i += 256) {
        int n = i / Dd, d = i - n * Dd;
        cs[i] = emb[(size_t)safe_id(cand_ids, m * Nn + n) * Dd + d];
    }
    for (int i = tid; i < CTX_L * Dd; i += 256) {
        int t = i / Dd, d = i - t * Dd;
        xs[i] = emb[(size_t)safe_id(ctx_ids, m * CTX_L + t) * Dd + d];
    }
    __syncthreads();

    for (int idx = tid; idx < Nn * CTX_L; idx += 256) {
        int n = idx / CTX_L, t = idx - n * CTX_L;
        const float* cp = cs + n * Dd;
        const float* xp = xs + t * Dd;
        float s = 0.f;
        for (int d = 0; d < Dd; d++) s = fmaf(cp[d], xp[d], s);
        tok[idx] = s;
    }
    __syncthreads();
    if (tid < CTX_L) {
        float mx = -1e30f;
        for (int n = 0; n < Nn; n++) mx = fmaxf(mx, tok[n * CTX_L + tid]);
        p[tid] = mx;
    }
    __syncthreads();
    if (tid < 32) {
        float mx = -1e30f;
        for (int t = tid; t < CTX_L; t += 32) mx = fmaxf(mx, p[t]);
        mx = warp_max(mx);
        float sum = 0.f;
        for (int t = tid; t < CTX_L; t += 32) {
            float e = expf(p[t] - mx);
            p[t] = e;
            sum += e;
        }
        sum = warp_sum(sum);
        float inv = 1.f / sum;
        for (int t = tid; t < CTX_L; t += 32) p[t] *= inv;
    }
    __syncthreads();
    for (int d = tid; d < Dd; d += 256) {
        float s = 0.f;
        for (int t = 0; t < CTX_L; t++) s = fmaf(p[t], xs[t * Dd + d], s);
        ctxv[d] = s;
    }
    __syncthreads();
    const int wid = tid >> 5, lane = tid & 31;
    for (int n = wid; n < Nn; n += 8) {
        float s = 0.f;
        for (int d = lane; d < Dd; d += 32) s = fmaf(cs[n * Dd + d], ctxv[d], s);
        s = warp_sum(s);
        if (lane == 0) g_local[m * Nn + n] = s;
    }
}

// ---------------- prep: title norms + cos(doc_bert, title) ----------------
__global__ void prep_kernel(const float* __restrict__ title,
                            const float* __restrict__ md) {
    const int w = threadIdx.x >> 5, lane = threadIdx.x & 31;  // 16 warps
    float st2 = 0.f, smt = 0.f, sm2 = 0.f;
    for (int j = lane; j < Ff; j += 32) {
        float t = title[w * Ff + j];
        float mv = md[j];
        st2 = fmaf(t, t, st2);
        smt = fmaf(t, mv, smt);
        sm2 = fmaf(mv, mv, sm2);
    }
    st2 = warp_sum(st2);
    smt = warp_sum(smt);
    sm2 = warp_sum(sm2);
    if (lane == 0) {
        float tnv = sqrtf(st2);
        g_tn[w] = tnv;
        g_cosdt[w] = smt / (fmaxf(sqrtf(sm2), 1e-6f) * fmaxf(tnv, 1e-6f));
    }
}

// ---------------- final: cos features, score, z / softmax / uniform ----------------
__global__ void final_kernel(const float* __restrict__ title,
                             const float* __restrict__ prior,
                             const float* __restrict__ hand,
                             const float* __restrict__ w7,
                             const float* __restrict__ b7,
                             float* __restrict__ out) {
    const int m = blockIdx.x;
    const int tid = threadIdx.x;  // 256
    const int wid = tid >> 5, lane = tid & 31;
    __shared__ float nms_s, nmc_s;
    __shared__ float dst[Nn], dct[Nn], sc[Nn];

    if (wid == 0) {
        float s = 0.f;
        for (int j = lane; j < Ff; j += 32) {
            float v = g_ms[m * Ff + j];
            s = fmaf(v, v, s);
        }
        s = warp_sum(s);
        if (lane == 0) nms_s = fmaxf(sqrtf(s), 1e-6f);
    }
    if (wid == 1) {
        float s = 0.f;
        for (int j = lane; j < Ff; j += 32) {
            float v = g_mc[m * Ff + j];
            s = fmaf(v, v, s);
        }
        s = warp_sum(s);
        if (lane == 0) nmc_s = fmaxf(sqrtf(s), 1e-6f);
    }
    for (int item = wid; item < 32; item += 8) {
        int n = item & 15;
        int which = item >> 4;
        const float* a = which ? (g_mc + m * Ff) : (g_ms + m * Ff);
        float s = 0.f;
        for (int j = lane; j < Ff; j += 32) s = fmaf(a[j], title[n * Ff + j], s);
        s = warp_sum(s);
        if (lane == 0) {
            if (which) dct[n] = s;
            else dst[n] = s;
        }
    }
    __syncthreads();

    if (tid < Nn) {
        int n = tid;
        float tc = fmaxf(g_tn[n], 1e-6f);
        float cst = dst[n] / (nms_s * tc);
        float cct = dct[n] / (nmc_s * tc);
        float s = b7[0];
        s = fmaf(w7[0], hand[n], s);
        s = fmaf(w7[1], prior[n], s);
        s = fmaf(w7[2], g_local[m * Nn + n], s);
        s = fmaf(w7[3], g_attscore[n], s);
        s = fmaf(w7[4], cst, s);
        s = fmaf(w7[5], g_cosdt[n], s);
        s = fmaf(w7[6], cct, s);
        sc[n] = s;
    }
    __syncthreads();
    if (tid < Nn) {
        float x = sc[tid];
        float mu = r16_sum(x) * (1.f / 16.f);
        float dv = x - mu;
        float var = r16_sum(dv * dv) * (1.f / 15.f);
        float z = dv / sqrtf(var);
        out[m * Nn + tid] = z;
        float zmax = r16_max(z);
        float zmin = r16_min(z);
        float e = expf(z - zmax);
        float es = r16_sum(e);
        out[Mm * Nn + m * Nn + tid] = e / es;
        float u = (z + 1.f - zmin) / (zmax - zmin);
        float us = r16_sum(u);
        out[2 * Mm * Nn + m * Nn + tid] = u / us;
    }
}

// ---------------- launch ----------------
extern "C" void kernel_launch(void* const* d_in, const int* in_sizes, int n_in,
                              void* d_out, int out_size) {
    // --- robust input location: anchor on the unique 30M-element embed table ---
    int e = -1;
    for (int i = 0; i < n_in; i++) {
        if (in_sizes[i] == VOCAB * Dd) { e = i; break; }
    }
    if (e < 0) e = 14;  // fallback: canonical order with scalars materialized

    const int* mention_vec  = (const int*)d_in[e - 11];
    const int* context_vec  = (const int*)d_in[e - 10];
    const int* doc_vec      = (const int*)d_in[e - 9];
    const float* title      = (const float*)d_in[e - 8];
    const int* body_vec     = (const int*)d_in[e - 7];
    const float* prior      = (const float*)d_in[e - 5];
    const int* men2cands    = (const int*)d_in[e - 4];
    const int* contexts_ids = (const int*)d_in[e - 3];
    const float* hand       = (const float*)d_in[e - 2];
    const float* bert       = (const float*)d_in[e - 1];
    const float* emb        = (const float*)d_in[e];
    const float* Wms        = (const float*)d_in[e + 1];
    const float* bms        = (const float*)d_in[e + 2];
    const float* Wmc        = (const float*)d_in[e + 3];
    const float* bmc        = (const float*)d_in[e + 4];
    const float* w7         = (const float*)d_in[e + 5];
    const float* b7         = (const float*)d_in[e + 6];
    const float* W1         = (const float*)d_in[e + 7];
    const float* b1         = (const float*)d_in[e + 8];
    const float* W2         = (const float*)d_in[e + 9];
    const float* b2         = (const float*)d_in[e + 10];
    float* out = (float*)d_out;

    // dynamic-smem opt-ins (idempotent, not stream ops — capture safe)
    cudaFuncSetAttribute(attn_kernel, cudaFuncAttributeMaxDynamicSharedMemorySize, 152000);
    cudaFuncSetAttribute(localctx_kernel, cudaFuncAttributeMaxDynamicSharedMemorySize, 84000);
    cudaFuncSetAttribute((const void*)conv_kernel<CTX_L, 5, 46, 23, 2, 1>,
                         cudaFuncAttributeMaxDynamicSharedMemorySize, 60032);

    // weight transposes
    transpose_w_kernel<2, 0><<<(2 * Dd * Ff + 255) / 256, 256>>>(Wms);
    transpose_w_kernel<5, 1><<<(5 * Dd * Ff + 255) / 256, 256>>>(Wmc);

    // convs
    conv_kernel<SURF_L, 2, 3, 3, 1, 0>
        <<<dim3(Mm, Ff / 128), 128, SURF_L * Dd * sizeof(float)>>>(mention_vec, emb, bms);
    conv_kernel<CTX_L, 5, 46, 23, 2, 1>
        <<<dim3(Mm, Ff / 256), 128, CTX_L * Dd * sizeof(float)>>>(context_vec, emb, bmc);

    // cross attention (16 n x 5 heads x 2 dirs)
    attn_kernel<<<dim3(Nn, NH, 2), 256, 152000>>>(doc_vec, body_vec, emb);

    // attention MLP score
    attmlp_kernel<<<Nn, 320>>>(W1, b1, W2, b2);

    // local context ranker
    localctx_kernel<<<Mm, 256, 84000>>>(men2cands, contexts_ids, emb);

    // title norms + cos(doc_bert, title)
    prep_kernel<<<1, 512>>>(title, bert);

    // final score + normalizations
    final_kernel<<<Mm, 256>>>(title, prior, hand, w7, b7, out);
}

// round 4
// speedup vs baseline: 2.7886x; 2.7886x over previous
#include <cuda_runtime.h>
#include <cuda_bf16.h>
#include <math.h>

#define Mm 64
#define Nn 16
#define Dd 300
#define Ff 768
#define VOCAB 100000
#define SURF_L 4
#define CTX_L 50
#define DOC_L 100
#define BODY_L 200
#define HD 60   // head dim
#define NH 5    // heads

// ---------------- scratch (__device__ globals, no allocation) ----------------
__device__ float g_Wt_ms[2 * Dd * Ff];      // [k][d][f]
__device__ float g_Wt_mc[5 * Dd * Ff];      // [k][d][f]
__device__ float g_part_mc[4 * Mm * Ff];    // t-block partial sums (sum of relu)
__device__ float g_part_ms[Mm * Ff];
__device__ float g_ms[Mm * Ff];
__device__ float g_mc[Mm * Ff];
__device__ float g_comb[Nn * 600];          // [n][dir*300 + h*60 + j]
__device__ float g_attscore[Nn];
__device__ float g_local[Mm * Nn];
__device__ float g_tn[Nn];
__device__ float g_cosdt[Nn];

// safe id fetch: clamp into valid vocab range so a bad index can never fault
__device__ __forceinline__ int safe_id(const int* p, int i) {
    int v = p[i];
    return v < 0 ? 0 : (v >= VOCAB ? VOCAB - 1 : v);
}

// ---------------- helpers ----------------
__device__ __forceinline__ float warp_sum(float v) {
#pragma unroll
    for (int o = 16; o; o >>= 1) v += __shfl_xor_sync(0xFFFFFFFFu, v, o);
    return v;
}
__device__ __forceinline__ float warp_max(float v) {
#pragma unroll
    for (int o = 16; o; o >>= 1) v = fmaxf(v, __shfl_xor_sync(0xFFFFFFFFu, v, o));
    return v;
}
__device__ __forceinline__ float r16_sum(float v) {
#pragma unroll
    for (int o = 8; o; o >>= 1) v += __shfl_xor_sync(0xFFFFu, v, o, 16);
    return v;
}
__device__ __forceinline__ float r16_max(float v) {
#pragma unroll
    for (int o = 8; o; o >>= 1) v = fmaxf(v, __shfl_xor_sync(0xFFFFu, v, o, 16));
    return v;
}
__device__ __forceinline__ float r16_min(float v) {
#pragma unroll
    for (int o = 8; o; o >>= 1) v = fminf(v, __shfl_xor_sync(0xFFFFu, v, o, 16));
    return v;
}

// ---------------- weight transpose: W[f][d][k] -> Wt[k][d][f] ----------------
template <int K, int WHICH>
__global__ void transpose_w_kernel(const float* __restrict__ W) {
    float* Wt = WHICH ? g_Wt_mc : g_Wt_ms;
    int idx = blockIdx.x * blockDim.x + threadIdx.x;
    const int total = K * Dd * Ff;
    if (idx < total) {
        int f = idx % Ff;
        int rest = idx / Ff;
        int d = rest % Dd;
        int k = rest / Dd;
        Wt[idx] = W[(size_t)f * Dd * K + d * K + k];
    }
}

// ---------------- conv1d(valid) + relu + sum over a t-block ----------------
// part[tb][m][f] = sum_{t in block tb} relu( b[f] + sum_{k,d} X[m][t+k][d]*W[f][d][k] )
// 192 threads, each owns 4 contiguous f (float4 weight loads), TC t-values in regs.
template <int L, int K, int T, int TC, int WHICH>
__launch_bounds__(192)
__global__ void conv2_kernel(const int* __restrict__ ids,
                             const float* __restrict__ emb,
                             const float* __restrict__ bias) {
    const float* __restrict__ Wt = WHICH ? g_Wt_mc : g_Wt_ms;
    float* __restrict__ part = WHICH ? g_part_mc : g_part_ms;
    const int m = blockIdx.x, tb = blockIdx.y;
    const int t0 = tb * TC;
    const int tid = threadIdx.x;

    __shared__ float Xs[(TC + K - 1) * Dd];
    for (int i = tid; i < (TC + K - 1) * Dd; i += 192) {
        int r = i / Dd, d = i - r * Dd;
        int l = t0 + r;
        Xs[i] = (l < L) ? emb[(size_t)safe_id(ids, m * L + l) * Dd + d] : 0.f;
    }
    __syncthreads();

    float4 acc[TC];
#pragma unroll
    for (int t = 0; t < TC; t++) acc[t] = make_float4(0.f, 0.f, 0.f, 0.f);

#pragma unroll
    for (int k = 0; k < K; k++) {
        const float4* __restrict__ wp =
            (const float4*)(Wt + (size_t)k * Dd * Ff) + tid;
        const float* __restrict__ xk = Xs + k * Dd;
#pragma unroll 4
        for (int d = 0; d < Dd; d++) {
            float4 w = wp[(size_t)d * (Ff / 4)];
#pragma unroll
            for (int t = 0; t < TC; t++) {
                float xv = xk[t * Dd + d];
                acc[t].x = fmaf(xv, w.x, acc[t].x);
                acc[t].y = fmaf(xv, w.y, acc[t].y);
                acc[t].z = fmaf(xv, w.z, acc[t].z);
                acc[t].w = fmaf(xv, w.w, acc[t].w);
            }
        }
    }

    float4 b4 = *((const float4*)bias + tid);
    float4 s = make_float4(0.f, 0.f, 0.f, 0.f);
#pragma unroll
    for (int t = 0; t < TC; t++) {
        if (t0 + t < T) {
            s.x += fmaxf(acc[t].x + b4.x, 0.f);
            s.y += fmaxf(acc[t].y + b4.y, 0.f);
            s.z += fmaxf(acc[t].z + b4.z, 0.f);
            s.w += fmaxf(acc[t].w + b4.w, 0.f);
        }
    }
    *((float4*)(part + ((size_t)tb * Mm + m) * Ff) + tid) = s;
}

// ---------------- combine conv partials -> g_ms, g_mc ----------------
__global__ void combine_kernel() {
    int idx = blockIdx.x * blockDim.x + threadIdx.x;
    if (idx < Mm * Ff) {
        g_mc[idx] = (g_part_mc[idx] + g_part_mc[Mm * Ff + idx] +
                     g_part_mc[2 * Mm * Ff + idx] + g_part_mc[3 * Mm * Ff + idx]) *
                    (1.0f / 46.0f);
        g_ms[idx] = g_part_ms[idx] * (1.0f / 3.0f);
    }
}

// ---------------- cross attention: per (n, head, dir), max over query ----------------
__global__ void attn_kernel(const int* __restrict__ doc_ids,
                            const int* __restrict__ body_ids,
                            const float* __restrict__ emb) {
    const int n = blockIdx.x, h = blockIdx.y, dir = blockIdx.z;
    const int Lq = dir == 0 ? DOC_L : BODY_L;
    const int Lk = dir == 0 ? BODY_L : DOC_L;
    extern __shared__ float sh[];
    float* qs = sh;               // Lq*HD
    float* ks = qs + Lq * HD;     // Lk*HD
    float* S = ks + Lk * HD;      // Lq*Lk
    __shared__ float red[60 * 4];

    const int tid = threadIdx.x;  // 256
    const int* qids = dir == 0 ? doc_ids : body_ids + n * BODY_L;
    const int* kids = dir == 0 ? body_ids + n * BODY_L : doc_ids;

    for (int i = tid; i < Lq * HD; i += 256) {
        int l = i / HD, j = i - l * HD;
        qs[i] = emb[(size_t)safe_id(qids, l) * Dd + h * HD + j];
    }
    for (int i = tid; i < Lk * HD; i += 256) {
        int l = i / HD, j = i - l * HD;
        ks[i] = emb[(size_t)safe_id(kids, l) * Dd + h * HD + j];
    }
    __syncthreads();

    const float scale = rsqrtf((float)HD);
    for (int idx = tid; idx < Lq * Lk; idx += 256) {
        int q = idx / Lk, k = idx - q * Lk;
        const float* qp = qs + q * HD;
        const float* kp = ks + k * HD;
        float s = 0.f;
#pragma unroll
        for (int j = 0; j < HD; j++) s = fmaf(qp[j], kp[j], s);
        S[idx] = s * scale;
    }
    __syncthreads();

    // row softmax: one warp per row
    const int wid = tid >> 5, lane = tid & 31;
    for (int q = wid; q < Lq; q += 8) {
        float* row = S + q * Lk;
        float mx = -1e30f;
        for (int k = lane; k < Lk; k += 32) mx = fmaxf(mx, row[k]);
        mx = warp_max(mx);
        float sum = 0.f;
        for (int k = lane; k < Lk; k += 32) {
            float e = expf(row[k] - mx);
            row[k] = e;
            sum += e;
        }
        sum = warp_sum(sum);
        float inv = 1.f / sum;
        for (int k = lane; k < Lk; k += 32) row[k] *= inv;
    }
    __syncthreads();

    // out[q][j] = sum_k P[q][k] * v[k][j]; then max over q (split into 4 q-groups)
    const int qper = Lq / 4;
    if (tid < 240) {
        int g = tid / 60, j = tid - g * 60;
        float mx = -1e30f;
        for (int q = g * qper; q < (g + 1) * qper; q++) {
            const float* row = S + q * Lk;
            float o = 0.f;
            for (int k = 0; k < Lk; k++) o = fmaf(row[k], ks[k * HD + j], o);
            mx = fmaxf(mx, o);
        }
        red[j * 4 + g] = mx;
    }
    __syncthreads();
    if (tid < 60) {
        float mx = fmaxf(fmaxf(red[tid * 4], red[tid * 4 + 1]),
                         fmaxf(red[tid * 4 + 2], red[tid * 4 + 3]));
        g_comb[n * 600 + dir * 300 + h * HD + tid] = mx;
    }
}

// ---------------- attention MLP: sigmoid(relu(comb@W1+b1)@W2+b2) ----------------
__global__ void attmlp_kernel(const float* __restrict__ W1,
                              const float* __restrict__ b1,
                              const float* __restrict__ W2,
                              const float* __restrict__ b2) {
    const int n = blockIdx.x;
    __shared__ float cb[600];
    __shared__ float partial[10];
    const int tid = threadIdx.x;  // 320
    for (int i = tid; i < 600; i += 320) cb[i] = g_comb[n * 600 + i];
    __syncthreads();
    float v = 0.f;
    if (tid < 300) {
        float a = b1[tid];
        for (int i = 0; i < 600; i++) a = fmaf(cb[i], W1[i * 300 + tid], a);
        a = fmaxf(a, 0.f);
        v = a * W2[tid];
    }
    v = warp_sum(v);
    if ((tid & 31) == 0) partial[tid >> 5] = v;
    __syncthreads();
    if (tid == 0) {
        float s = 0.f;
        for (int w = 0; w < 10; w++) s += partial[w];
        s += b2[0];
        g_attscore[n] = 1.f / (1.f + expf(-s));
    }
}

// ---------------- LocalCtxAttRanker ----------------
__global__ void localctx_kernel(const int* __restrict__ cand_ids,
                                const int* __restrict__ ctx_ids,
                                const float* __restrict__ emb) {
    const int m = blockIdx.x;
    extern __shared__ float sh[];
    float* cs = sh;                 // 16*300
    float* xs = cs + Nn * Dd;       // 50*300
    float* tok = xs + CTX_L * Dd;   // 16*50
    float* p = tok + Nn * CTX_L;    // 50
    float* ctxv = p + CTX_L;        // 300
    const int tid = threadIdx.x;    // 256

    for (int i = tid; i < Nn * Dd; i += 256) {
        int n = i / Dd, d = i - n * Dd;
        cs[i] = emb[(size_t)safe_id(cand_ids, m * Nn + n) * Dd + d];
    }
    for (int i = tid; i < CTX_L * Dd; i += 256) {
        int t = i / Dd, d = i - t * Dd;
        xs[i] = emb[(size_t)safe_id(ctx_ids, m * CTX_L + t) * Dd + d];
    }
    __syncthreads();

    for (int idx = tid; idx < Nn * CTX_L; idx += 256) {
        int n = idx / CTX_L, t = idx - n * CTX_L;
        const float* cp = cs + n * Dd;
        const float* xp = xs + t * Dd;
        float s = 0.f;
        for (int d = 0; d < Dd; d++) s = fmaf(cp[d], xp[d], s);
        tok[idx] = s;
    }
    __syncthreads();
    if (tid < CTX_L) {
        float mx = -1e30f;
        for (int n = 0; n < Nn; n++) mx = fmaxf(mx, tok[n * CTX_L + tid]);
        p[tid] = mx;
    }
    __syncthreads();
    if (tid < 32) {
        float mx = -1e30f;
        for (int t = tid; t < CTX_L; t += 32) mx = fmaxf(mx, p[t]);
        mx = warp_max(mx);
        float sum = 0.f;
        for (int t = tid; t < CTX_L; t += 32) {
            float e = expf(p[t] - mx);
            p[t] = e;
            sum += e;
        }
        sum = warp_sum(sum);
        float inv = 1.f / sum;
        for (int t = tid; t < CTX_L; t += 32) p[t] *= inv;
    }
    __syncthreads();
    for (int d = tid; d < Dd; d += 256) {
        float s = 0.f;
        for (int t = 0; t < CTX_L; t++) s = fmaf(p[t], xs[t * Dd + d], s);
        ctxv[d] = s;
    }
    __syncthreads();
    const int wid = tid >> 5, lane = tid & 31;
    for (int n = wid; n < Nn; n += 8) {
        float s = 0.f;
        for (int d = lane; d < Dd; d += 32) s = fmaf(cs[n * Dd + d], ctxv[d], s);
        s = warp_sum(s);
        if (lane == 0) g_local[m * Nn + n] = s;
    }
}

// ---------------- prep: title norms + cos(doc_bert, title) ----------------
__global__ void prep_kernel(const float* __restrict__ title,
                            const float* __restrict__ md) {
    const int w = threadIdx.x >> 5, lane = threadIdx.x & 31;  // 16 warps
    float st2 = 0.f, smt = 0.f, sm2 = 0.f;
    for (int j = lane; j < Ff; j += 32) {
        float t = title[w * Ff + j];
        float mv = md[j];
        st2 = fmaf(t, t, st2);
        smt = fmaf(t, mv, smt);
        sm2 = fmaf(mv, mv, sm2);
    }
    st2 = warp_sum(st2);
    smt = warp_sum(smt);
    sm2 = warp_sum(sm2);
    if (lane == 0) {
        float tnv = sqrtf(st2);
        g_tn[w] = tnv;
        g_cosdt[w] = smt / (fmaxf(sqrtf(sm2), 1e-6f) * fmaxf(tnv, 1e-6f));
    }
}

// ---------------- final: cos features, score, z / softmax / uniform ----------------
__global__ void final_kernel(const float* __restrict__ title,
                             const float* __restrict__ prior,
                             const float* __restrict__ hand,
                             const float* __restrict__ w7,
                             const float* __restrict__ b7,
                             float* __restrict__ out) {
    const int m = blockIdx.x;
    const int tid = threadIdx.x;  // 256
    const int wid = tid >> 5, lane = tid & 31;
    __shared__ float nms_s, nmc_s;
    __shared__ float dst[Nn], dct[Nn], sc[Nn];

    if (wid == 0) {
        float s = 0.f;
        for (int j = lane; j < Ff; j += 32) {
            float v = g_ms[m * Ff + j];
            s = fmaf(v, v, s);
        }
        s = warp_sum(s);
        if (lane == 0) nms_s = fmaxf(sqrtf(s), 1e-6f);
    }
    if (wid == 1) {
        float s = 0.f;
        for (int j = lane; j < Ff; j += 32) {
            float v = g_mc[m * Ff + j];
            s = fmaf(v, v, s);
        }
        s = warp_sum(s);
        if (lane == 0) nmc_s = fmaxf(sqrtf(s), 1e-6f);
    }
    for (int item = wid; item < 32; item += 8) {
        int n = item & 15;
        int which = item >> 4;
        const float* a = which ? (g_mc + m * Ff) : (g_ms + m * Ff);
        float s = 0.f;
        for (int j = lane; j < Ff; j += 32) s = fmaf(a[j], title[n * Ff + j], s);
        s = warp_sum(s);
        if (lane == 0) {
            if (which) dct[n] = s;
            else dst[n] = s;
        }
    }
    __syncthreads();

    if (tid < Nn) {
        int n = tid;
        float tc = fmaxf(g_tn[n], 1e-6f);
        float cst = dst[n] / (nms_s * tc);
        float cct = dct[n] / (nmc_s * tc);
        float s = b7[0];
        s = fmaf(w7[0], hand[n], s);
        s = fmaf(w7[1], prior[n], s);
        s = fmaf(w7[2], g_local[m * Nn + n], s);
        s = fmaf(w7[3], g_attscore[n], s);
        s = fmaf(w7[4], cst, s);
        s = fmaf(w7[5], g_cosdt[n], s);
        s = fmaf(w7[6], cct, s);
        sc[n] = s;
    }
    __syncthreads();
    if (tid < Nn) {
        float x = sc[tid];
        float mu = r16_sum(x) * (1.f / 16.f);
        float dv = x - mu;
        float var = r16_sum(dv * dv) * (1.f / 15.f);
        float z = dv / sqrtf(var);
        out[m * Nn + tid] = z;
        float zmax = r16_max(z);
        float zmin = r16_min(z);
        float e = expf(z - zmax);
        float es = r16_sum(e);
        out[Mm * Nn + m * Nn + tid] = e / es;
        float u = (z + 1.f - zmin) / (zmax - zmin);
        float us = r16_sum(u);
        out[2 * Mm * Nn + m * Nn + tid] = u / us;
    }
}

// ---------------- launch ----------------
extern "C" void kernel_launch(void* const* d_in, const int* in_sizes, int n_in,
                              void* d_out, int out_size) {
    // --- robust input location: anchor on the unique 30M-element embed table ---
    int e = -1;
    for (int i = 0; i < n_in; i++) {
        if (in_sizes[i] == VOCAB * Dd) { e = i; break; }
    }
    if (e < 0) e = 14;  // fallback: canonical order with scalars materialized

    const int* mention_vec  = (const int*)d_in[e - 11];
    const int* context_vec  = (const int*)d_in[e - 10];
    const int* doc_vec      = (const int*)d_in[e - 9];
    const float* title      = (const float*)d_in[e - 8];
    const int* body_vec     = (const int*)d_in[e - 7];
    const float* prior      = (const float*)d_in[e - 5];
    const int* men2cands    = (const int*)d_in[e - 4];
    const int* contexts_ids = (const int*)d_in[e - 3];
    const float* hand       = (const float*)d_in[e - 2];
    const float* bert       = (const float*)d_in[e - 1];
    const float* emb        = (const float*)d_in[e];
    const float* Wms        = (const float*)d_in[e + 1];
    const float* bms        = (const float*)d_in[e + 2];
    const float* Wmc        = (const float*)d_in[e + 3];
    const float* bmc        = (const float*)d_in[e + 4];
    const float* w7         = (const float*)d_in[e + 5];
    const float* b7         = (const float*)d_in[e + 6];
    const float* W1         = (const float*)d_in[e + 7];
    const float* b1         = (const float*)d_in[e + 8];
    const float* W2         = (const float*)d_in[e + 9];
    const float* b2         = (const float*)d_in[e + 10];
    float* out = (float*)d_out;

    // dynamic-smem opt-ins (idempotent, not stream ops — capture safe)
    cudaFuncSetAttribute(attn_kernel, cudaFuncAttributeMaxDynamicSharedMemorySize, 152000);
    cudaFuncSetAttribute(localctx_kernel, cudaFuncAttributeMaxDynamicSharedMemorySize, 84000);

    // weight transposes
    transpose_w_kernel<2, 0><<<(2 * Dd * Ff + 255) / 256, 256>>>(Wms);
    transpose_w_kernel<5, 1><<<(5 * Dd * Ff + 255) / 256, 256>>>(Wmc);

    // convs: float4-f per thread, T split across grid.y, partial sums
    conv2_kernel<SURF_L, 2, 3, 3, 0><<<dim3(Mm, 1), 192>>>(mention_vec, emb, bms);
    conv2_kernel<CTX_L, 5, 46, 12, 1><<<dim3(Mm, 4), 192>>>(context_vec, emb, bmc);

    // cross attention (16 n x 5 heads x 2 dirs)
    attn_kernel<<<dim3(Nn, NH, 2), 256, 152000>>>(doc_vec, body_vec, emb);

    // attention MLP score
    attmlp_kernel<<<Nn, 320>>>(W1, b1, W2, b2);

    // local context ranker
    localctx_kernel<<<Mm, 256, 84000>>>(men2cands, contexts_ids, emb);

    // title norms + cos(doc_bert, title)
    prep_kernel<<<1, 512>>>(title, bert);

    // combine conv partials
    combine_kernel<<<(Mm * Ff + 255) / 256, 256>>>();

    // final score + normalizations
    final_kernel<<<Mm, 256>>>(title, prior, hand, w7, b7, out);
}

// round 5
// speedup vs baseline: 2.7896x; 1.0003x over previous
#include <cuda_runtime.h>
#include <cuda_bf16.h>
#include <math.h>

#define Mm 64
#define Nn 16
#define Dd 300
#define Ff 768
#define VOCAB 100000
#define SURF_L 4
#define CTX_L 50
#define DOC_L 100
#define BODY_L 200
#define HD 60   // head dim
#define NH 5    // heads

typedef unsigned long long u64;

// ---------------- scratch (__device__ globals, no allocation) ----------------
__device__ float g_Wt_ms[2 * Dd * Ff];      // [k][d][f]
__device__ float g_Wt_mc[5 * Dd * Ff];      // [k][d][f]
__device__ float g_part_mc[3 * Mm * Ff];    // t-block partial sums (sum of relu)
__device__ float g_part_ms[Mm * Ff];
__device__ float g_ms[Mm * Ff];
__device__ float g_mc[Mm * Ff];
__device__ float g_comb[Nn * 600];          // [n][dir*300 + h*60 + j]
__device__ float g_attscore[Nn];
__device__ float g_local[Mm * Nn];
__device__ float g_tn[Nn];
__device__ float g_cosdt[Nn];

// safe id fetch: clamp into valid vocab range so a bad index can never fault
__device__ __forceinline__ int safe_id(const int* p, int i) {
    int v = p[i];
    return v < 0 ? 0 : (v >= VOCAB ? VOCAB - 1 : v);
}

// ---------------- f32x2 packed math ----------------
__device__ __forceinline__ void ffma2(u64& a, u64 x, u64 w) {
    asm("fma.rn.f32x2 %0, %1, %2, %0;" : "+l"(a) : "l"(x), "l"(w));
}
__device__ __forceinline__ float2 unpack2(u64 v) {
    float2 r;
    asm("mov.b64 {%0,%1}, %2;" : "=f"(r.x), "=f"(r.y) : "l"(v));
    return r;
}
__device__ __forceinline__ u64 pack2(float a, float b) {
    u64 r;
    asm("mov.b64 %0, {%1,%2};" : "=l"(r) : "f"(a), "f"(b));
    return r;
}

// ---------------- helpers ----------------
__device__ __forceinline__ float warp_sum(float v) {
#pragma unroll
    for (int o = 16; o; o >>= 1) v += __shfl_xor_sync(0xFFFFFFFFu, v, o);
    return v;
}
__device__ __forceinline__ float warp_max(float v) {
#pragma unroll
    for (int o = 16; o; o >>= 1) v = fmaxf(v, __shfl_xor_sync(0xFFFFFFFFu, v, o));
    return v;
}
__device__ __forceinline__ float r16_sum(float v) {
#pragma unroll
    for (int o = 8; o; o >>= 1) v += __shfl_xor_sync(0xFFFFu, v, o, 16);
    return v;
}
__device__ __forceinline__ float r16_max(float v) {
#pragma unroll
    for (int o = 8; o; o >>= 1) v = fmaxf(v, __shfl_xor_sync(0xFFFFu, v, o, 16));
    return v;
}
__device__ __forceinline__ float r16_min(float v) {
#pragma unroll
    for (int o = 8; o; o >>= 1) v = fminf(v, __shfl_xor_sync(0xFFFFu, v, o, 16));
    return v;
}

// ---------------- merged weight transpose: W[f][d][k] -> Wt[k][d][f] ----------------
__global__ void transpose_all_kernel(const float* __restrict__ Wms,
                                     const float* __restrict__ Wmc) {
    int idx = blockIdx.x * blockDim.x + threadIdx.x;
    const int totA = 2 * Dd * Ff;
    const int totB = 5 * Dd * Ff;
    if (idx < totA) {
        int f = idx % Ff;
        int rest = idx / Ff;
        int d = rest % Dd;
        int k = rest / Dd;
        g_Wt_ms[idx] = Wms[(size_t)f * Dd * 2 + d * 2 + k];
    } else if (idx < totA + totB) {
        int i = idx - totA;
        int f = i % Ff;
        int rest = i / Ff;
        int d = rest % Dd;
        int k = rest / Dd;
        g_Wt_mc[i] = Wmc[(size_t)f * Dd * 5 + d * 5 + k];
    }
}

// ---------------- conv1d(valid) + relu + sum over a t-block, FFMA2 ----------------
// part[tb][m][f] = sum_{t in block tb} relu( b[f] + sum_{k,d} X[m][t+k][d]*W[f][d][k] )
// 192 threads; each owns 4 contiguous f. Weights loaded as ulonglong2 (= float4),
// X pre-duplicated in smem as (x,x) so one LDS.64 feeds both FFMA2 halves.
template <int L, int K, int T, int TC, int WHICH>
__launch_bounds__(192)
__global__ void conv3_kernel(const int* __restrict__ ids,
                             const float* __restrict__ emb,
                             const float* __restrict__ bias) {
    const float* __restrict__ Wt = WHICH ? g_Wt_mc : g_Wt_ms;
    float* __restrict__ part = WHICH ? g_part_mc : g_part_ms;
    const int m = blockIdx.x, tb = blockIdx.y;
    const int t0 = tb * TC;
    const int tid = threadIdx.x;

    __shared__ float2 Xs[(TC + K - 1) * Dd];   // duplicated pairs (x,x)
    for (int i = tid; i < (TC + K - 1) * Dd; i += 192) {
        int r = i / Dd, d = i - r * Dd;
        int l = t0 + r;
        float v = (l < L) ? emb[(size_t)safe_id(ids, m * L + l) * Dd + d] : 0.f;
        Xs[i] = make_float2(v, v);
    }
    __syncthreads();

    u64 acc[TC][2];
#pragma unroll
    for (int t = 0; t < TC; t++) { acc[t][0] = 0ull; acc[t][1] = 0ull; }

#pragma unroll
    for (int k = 0; k < K; k++) {
        const ulonglong2* __restrict__ wp =
            (const ulonglong2*)(Wt + (size_t)k * Dd * Ff) + tid;
        const float2* __restrict__ xk = Xs + k * Dd;
#pragma unroll 2
        for (int d = 0; d < Dd; d++) {
            ulonglong2 w = wp[(size_t)d * (Ff / 4)];
#pragma unroll
            for (int t = 0; t < TC; t++) {
                u64 x2 = *(const u64*)(xk + t * Dd + d);
                ffma2(acc[t][0], x2, w.x);
                ffma2(acc[t][1], x2, w.y);
            }
        }
    }

    float4 b4 = ((const float4*)bias)[tid];
    float4 s = make_float4(0.f, 0.f, 0.f, 0.f);
#pragma unroll
    for (int t = 0; t < TC; t++) {
        if (t0 + t < T) {
            float2 p0 = unpack2(acc[t][0]);
            float2 p1 = unpack2(acc[t][1]);
            s.x += fmaxf(p0.x + b4.x, 0.f);
            s.y += fmaxf(p0.y + b4.y, 0.f);
            s.z += fmaxf(p1.x + b4.z, 0.f);
            s.w += fmaxf(p1.y + b4.w, 0.f);
        }
    }
    ((float4*)(part + ((size_t)tb * Mm + m) * Ff))[tid] = s;
}

// ---------------- combine conv partials -> g_ms, g_mc ----------------
__global__ void combine_kernel() {
    int idx = blockIdx.x * blockDim.x + threadIdx.x;
    if (idx < Mm * Ff) {
        g_mc[idx] = (g_part_mc[idx] + g_part_mc[Mm * Ff + idx] +
                     g_part_mc[2 * Mm * Ff + idx]) * (1.0f / 46.0f);
        g_ms[idx] = g_part_ms[idx] * (1.0f / 3.0f);
    }
}

// ---------------- cross attention: per (n, head, dir), max over query ----------------
__global__ void attn_kernel(const int* __restrict__ doc_ids,
                            const int* __restrict__ body_ids,
                            const float* __restrict__ emb) {
    const int n = blockIdx.x, h = blockIdx.y, dir = blockIdx.z;
    const int Lq = dir == 0 ? DOC_L : BODY_L;
    const int Lk = dir == 0 ? BODY_L : DOC_L;
    extern __shared__ float sh[];
    float* qs = sh;               // Lq*HD (16B aligned: 60*4=240B rows)
    float* ks = qs + Lq * HD;     // Lk*HD
    float* S = ks + Lk * HD;      // Lq*Lk
    __shared__ float red[60 * 16];

    const int tid = threadIdx.x;  // 256
    const int* qids = dir == 0 ? doc_ids : body_ids + n * BODY_L;
    const int* kids = dir == 0 ? body_ids + n * BODY_L : doc_ids;

    for (int i = tid; i < Lq * HD; i += 256) {
        int l = i / HD, j = i - l * HD;
        qs[i] = emb[(size_t)safe_id(qids, l) * Dd + h * HD + j];
    }
    for (int i = tid; i < Lk * HD; i += 256) {
        int l = i / HD, j = i - l * HD;
        ks[i] = emb[(size_t)safe_id(kids, l) * Dd + h * HD + j];
    }
    __syncthreads();

    const float scale = rsqrtf((float)HD);
    for (int idx = tid; idx < Lq * Lk; idx += 256) {
        int q = idx / Lk, k = idx - q * Lk;
        const ulonglong2* qp = (const ulonglong2*)(qs + q * HD);
        const ulonglong2* kp = (const ulonglong2*)(ks + k * HD);
        u64 a0 = 0ull, a1 = 0ull;
#pragma unroll
        for (int j = 0; j < HD / 4; j++) {
            ulonglong2 qv = qp[j];
            ulonglong2 kv = kp[j];
            ffma2(a0, qv.x, kv.x);
            ffma2(a1, qv.y, kv.y);
        }
        float2 fa = unpack2(a0), fb = unpack2(a1);
        S[idx] = (fa.x + fa.y + fb.x + fb.y) * scale;
    }
    __syncthreads();

    // row softmax: one warp per row
    const int wid = tid >> 5, lane = tid & 31;
    for (int q = wid; q < Lq; q += 8) {
        float* row = S + q * Lk;
        float mx = -1e30f;
        for (int k = lane; k < Lk; k += 32) mx = fmaxf(mx, row[k]);
        mx = warp_max(mx);
        float sum = 0.f;
        for (int k = lane; k < Lk; k += 32) {
            float e = expf(row[k] - mx);
            row[k] = e;
            sum += e;
        }
        sum = warp_sum(sum);
        float inv = 1.f / sum;
        for (int k = lane; k < Lk; k += 32) row[k] *= inv;
    }
    __syncthreads();

    // out[q][j] = sum_k P[q][k] * v[k][j]; max over q.
    // 240 threads = 16 q-groups x 15 j4-groups (4 j each), FFMA2 on float4 V rows.
    if (tid < 240) {
        int qg = tid / 15;            // 0..15
        int j4 = tid - qg * 15;       // 0..14
        float4 mx = make_float4(-1e30f, -1e30f, -1e30f, -1e30f);
        for (int q = qg; q < Lq; q += 16) {
            const float* row = S + q * Lk;
            u64 o0 = 0ull, o1 = 0ull;
#pragma unroll 4
            for (int k = 0; k < Lk; k++) {
                float xv = row[k];
                u64 x2 = pack2(xv, xv);
                ulonglong2 v = *(const ulonglong2*)(ks + k * HD + j4 * 4);
                ffma2(o0, x2, v.x);
                ffma2(o1, x2, v.y);
            }
            float2 f0 = unpack2(o0), f1 = unpack2(o1);
            mx.x = fmaxf(mx.x, f0.x);
            mx.y = fmaxf(mx.y, f0.y);
            mx.z = fmaxf(mx.z, f1.x);
            mx.w = fmaxf(mx.w, f1.y);
        }
        red[(j4 * 4 + 0) * 16 + qg] = mx.x;
        red[(j4 * 4 + 1) * 16 + qg] = mx.y;
        red[(j4 * 4 + 2) * 16 + qg] = mx.z;
        red[(j4 * 4 + 3) * 16 + qg] = mx.w;
    }
    __syncthreads();
    if (tid < 60) {
        float mxv = -1e30f;
#pragma unroll
        for (int g = 0; g < 16; g++) mxv = fmaxf(mxv, red[tid * 16 + g]);
        g_comb[n * 600 + dir * 300 + h * HD + tid] = mxv;
    }
}

// ---------------- attention MLP: sigmoid(relu(comb@W1+b1)@W2+b2) ----------------
__global__ void attmlp_kernel(const float* __restrict__ W1,
                              const float* __restrict__ b1,
                              const float* __restrict__ W2,
                              const float* __restrict__ b2) {
    const int n = blockIdx.x;
    __shared__ float cb[600];
    __shared__ float partial[10];
    const int tid = threadIdx.x;  // 320
    for (int i = tid; i < 600; i += 320) cb[i] = g_comb[n * 600 + i];
    __syncthreads();
    float v = 0.f;
    if (tid < 300) {
        float a = b1[tid];
        for (int i = 0; i < 600; i++) a = fmaf(cb[i], W1[i * 300 + tid], a);
        a = fmaxf(a, 0.f);
        v = a * W2[tid];
    }
    v = warp_sum(v);
    if ((tid & 31) == 0) partial[tid >> 5] = v;
    __syncthreads();
    if (tid == 0) {
        float s = 0.f;
        for (int w = 0; w < 10; w++) s += partial[w];
        s += b2[0];
        g_attscore[n] = 1.f / (1.f + expf(-s));
    }
}

// ---------------- LocalCtxAttRanker ----------------
__global__ void localctx_kernel(const int* __restrict__ cand_ids,
                                const int* __restrict__ ctx_ids,
                                const float* __restrict__ emb) {
    const int m = blockIdx.x;
    extern __shared__ float sh[];
    float* cs = sh;                 // 16*300
    float* xs = cs + Nn * Dd;       // 50*300
    float* tok = xs + CTX_L * Dd;   // 16*50
    float* p = tok + Nn * CTX_L;    // 50
    float* ctxv = p + CTX_L;        // 300
    const int tid = threadIdx.x;    // 256

    for (int i = tid; i < Nn * Dd; i += 256) {
        int n = i / Dd, d = i - n * Dd;
        cs[i] = emb[(size_t)safe_id(cand_ids, m * Nn + n) * Dd + d];
    }
    for (int i = tid; i < CTX_L * Dd; i += 256) {
        int t = i / Dd, d = i - t * Dd;
        xs[i] = emb[(size_t)safe_id(ctx_ids, m * CTX_L + t) * Dd + d];
    }
    __syncthreads();

    for (int idx = tid; idx < Nn * CTX_L; idx += 256) {
        int n = idx / CTX_L, t = idx - n * CTX_L;
        const float* cp = cs + n * Dd;
        const float* xp = xs + t * Dd;
        float s = 0.f;
        for (int d = 0; d < Dd; d++) s = fmaf(cp[d], xp[d], s);
        tok[idx] = s;
    }
    __syncthreads();
    if (tid < CTX_L) {
        float mx = -1e30f;
        for (int n = 0; n < Nn; n++) mx = fmaxf(mx, tok[n * CTX_L + tid]);
        p[tid] = mx;
    }
    __syncthreads();
    if (tid < 32) {
        float mx = -1e30f;
        for (int t = tid; t < CTX_L; t += 32) mx = fmaxf(mx, p[t]);
        mx = warp_max(mx);
        float sum = 0.f;
        for (int t = tid; t < CTX_L; t += 32) {
            float e = expf(p[t] - mx);
            p[t] = e;
            sum += e;
        }
        sum = warp_sum(sum);
        float inv = 1.f / sum;
        for (int t = tid; t < CTX_L; t += 32) p[t] *= inv;
    }
    __syncthreads();
    for (int d = tid; d < Dd; d += 256) {
        float s = 0.f;
        for (int t = 0; t < CTX_L; t++) s = fmaf(p[t], xs[t * Dd + d], s);
        ctxv[d] = s;
    }
    __syncthreads();
    const int wid = tid >> 5, lane = tid & 31;
    for (int n = wid; n < Nn; n += 8) {
        float s = 0.f;
        for (int d = lane; d < Dd; d += 32) s = fmaf(cs[n * Dd + d], ctxv[d], s);
        s = warp_sum(s);
        if (lane == 0) g_local[m * Nn + n] = s;
    }
}

// ---------------- prep: title norms + cos(doc_bert, title) ----------------
__global__ void prep_kernel(const float* __restrict__ title,
                            const float* __restrict__ md) {
    const int w = threadIdx.x >> 5, lane = threadIdx.x & 31;  // 16 warps
    float st2 = 0.f, smt = 0.f, sm2 = 0.f;
    for (int j = lane; j < Ff; j += 32) {
        float t = title[w * Ff + j];
        float mv = md[j];
        st2 = fmaf(t, t, st2);
        smt = fmaf(t, mv, smt);
        sm2 = fmaf(mv, mv, sm2);
    }
    st2 = warp_sum(st2);
    smt = warp_sum(smt);
    sm2 = warp_sum(sm2);
    if (lane == 0) {
        float tnv = sqrtf(st2);
        g_tn[w] = tnv;
        g_cosdt[w] = smt / (fmaxf(sqrtf(sm2), 1e-6f) * fmaxf(tnv, 1e-6f));
    }
}

// ---------------- final: cos features, score, z / softmax / uniform ----------------
__global__ void final_kernel(const float* __restrict__ title,
                             const float* __restrict__ prior,
                             const float* __restrict__ hand,
                             const float* __restrict__ w7,
                             const float* __restrict__ b7,
                             float* __restrict__ out) {
    const int m = blockIdx.x;
    const int tid = threadIdx.x;  // 256
    const int wid = tid >> 5, lane = tid & 31;
    __shared__ float nms_s, nmc_s;
    __shared__ float dst[Nn], dct[Nn], sc[Nn];

    if (wid == 0) {
        float s = 0.f;
        for (int j = lane; j < Ff; j += 32) {
            float v = g_ms[m * Ff + j];
            s = fmaf(v, v, s);
        }
        s = warp_sum(s);
        if (lane == 0) nms_s = fmaxf(sqrtf(s), 1e-6f);
    }
    if (wid == 1) {
        float s = 0.f;
        for (int j = lane; j < Ff; j += 32) {
            float v = g_mc[m * Ff + j];
            s = fmaf(v, v, s);
        }
        s = warp_sum(s);
        if (lane == 0) nmc_s = fmaxf(sqrtf(s), 1e-6f);
    }
    for (int item = wid; item < 32; item += 8) {
        int n = item & 15;
        int which = item >> 4;
        const float* a = which ? (g_mc + m * Ff) : (g_ms + m * Ff);
        float s = 0.f;
        for (int j = lane; j < Ff; j += 32) s = fmaf(a[j], title[n * Ff + j], s);
        s = warp_sum(s);
        if (lane == 0) {
            if (which) dct[n] = s;
            else dst[n] = s;
        }
    }
    __syncthreads();

    if (tid < Nn) {
        int n = tid;
        float tc = fmaxf(g_tn[n], 1e-6f);
        float cst = dst[n] / (nms_s * tc);
        float cct = dct[n] / (nmc_s * tc);
        float s = b7[0];
        s = fmaf(w7[0], hand[n], s);
        s = fmaf(w7[1], prior[n], s);
        s = fmaf(w7[2], g_local[m * Nn + n], s);
        s = fmaf(w7[3], g_attscore[n], s);
        s = fmaf(w7[4], cst, s);
        s = fmaf(w7[5], g_cosdt[n], s);
        s = fmaf(w7[6], cct, s);
        sc[n] = s;
    }
    __syncthreads();
    if (tid < Nn) {
        float x = sc[tid];
        float mu = r16_sum(x) * (1.f / 16.f);
        float dv = x - mu;
        float var = r16_sum(dv * dv) * (1.f / 15.f);
        float z = dv / sqrtf(var);
        out[m * Nn + tid] = z;
        float zmax = r16_max(z);
        float zmin = r16_min(z);
        float e = expf(z - zmax);
        float es = r16_sum(e);
        out[Mm * Nn + m * Nn + tid] = e / es;
        float u = (z + 1.f - zmin) / (zmax - zmin);
        float us = r16_sum(u);
        out[2 * Mm * Nn + m * Nn + tid] = u / us;
    }
}

// ---------------- launch ----------------
extern "C" void kernel_launch(void* const* d_in, const int* in_sizes, int n_in,
                              void* d_out, int out_size) {
    // --- robust input location: anchor on the unique 30M-element embed table ---
    int e = -1;
    for (int i = 0; i < n_in; i++) {
        if (in_sizes[i] == VOCAB * Dd) { e = i; break; }
    }
    if (e < 0) e = 14;  // fallback: canonical order with scalars materialized

    const int* mention_vec  = (const int*)d_in[e - 11];
    const int* context_vec  = (const int*)d_in[e - 10];
    const int* doc_vec      = (const int*)d_in[e - 9];
    const float* title      = (const float*)d_in[e - 8];
    const int* body_vec     = (const int*)d_in[e - 7];
    const float* prior      = (const float*)d_in[e - 5];
    const int* men2cands    = (const int*)d_in[e - 4];
    const int* contexts_ids = (const int*)d_in[e - 3];
    const float* hand       = (const float*)d_in[e - 2];
    const float* bert       = (const float*)d_in[e - 1];
    const float* emb        = (const float*)d_in[e];
    const float* Wms        = (const float*)d_in[e + 1];
    const float* bms        = (const float*)d_in[e + 2];
    const float* Wmc        = (const float*)d_in[e + 3];
    const float* bmc        = (const float*)d_in[e + 4];
    const float* w7         = (const float*)d_in[e + 5];
    const float* b7         = (const float*)d_in[e + 6];
    const float* W1         = (const float*)d_in[e + 7];
    const float* b1         = (const float*)d_in[e + 8];
    const float* W2         = (const float*)d_in[e + 9];
    const float* b2         = (const float*)d_in[e + 10];
    float* out = (float*)d_out;

    // one-time host-side resources (created on the first, non-captured call)
    static bool s_init = false;
    static cudaStream_t s1, s2;
    static cudaEvent_t evF, ev1, ev2;
    if (!s_init) {
        cudaStreamCreateWithFlags(&s1, cudaStreamNonBlocking);
        cudaStreamCreateWithFlags(&s2, cudaStreamNonBlocking);
        cudaEventCreateWithFlags(&evF, cudaEventDisableTiming);
        cudaEventCreateWithFlags(&ev1, cudaEventDisableTiming);
        cudaEventCreateWithFlags(&ev2, cudaEventDisableTiming);
        s_init = true;
    }

    // dynamic-smem opt-ins (idempotent, not stream ops — capture safe)
    cudaFuncSetAttribute(attn_kernel, cudaFuncAttributeMaxDynamicSharedMemorySize, 152000);
    cudaFuncSetAttribute(localctx_kernel, cudaFuncAttributeMaxDynamicSharedMemorySize, 84000);

    // fork
    cudaEventRecord(evF, 0);
    cudaStreamWaitEvent(s1, evF, 0);
    cudaStreamWaitEvent(s2, evF, 0);

    // s1: cross attention + MLP score
    attn_kernel<<<dim3(Nn, NH, 2), 256, 152000, s1>>>(doc_vec, body_vec, emb);
    attmlp_kernel<<<Nn, 320, 0, s1>>>(W1, b1, W2, b2);
    cudaEventRecord(ev1, s1);

    // s2: local context ranker + title prep
    localctx_kernel<<<Mm, 256, 84000, s2>>>(men2cands, contexts_ids, emb);
    prep_kernel<<<1, 512, 0, s2>>>(title, bert);
    cudaEventRecord(ev2, s2);

    // main stream: transpose -> convs (FFMA2) -> combine
    transpose_all_kernel<<<(7 * Dd * Ff + 255) / 256, 256>>>(Wms, Wmc);
    conv3_kernel<SURF_L, 2, 3, 4, 0><<<dim3(Mm, 1), 192>>>(mention_vec, emb, bms);
    conv3_kernel<CTX_L, 5, 46, 16, 1><<<dim3(Mm, 3), 192>>>(context_vec, emb, bmc);
    combine_kernel<<<(Mm * Ff + 255) / 256, 256>>>();

    // join
    cudaStreamWaitEvent(0, ev1, 0);
    cudaStreamWaitEvent(0, ev2, 0);

    // final score + normalizations
    final_kernel<<<Mm, 256>>>(title, prior, hand, w7, b7, out);
}

// round 8
// speedup vs baseline: 3.2476x; 1.1642x over previous
#include <cuda_runtime.h>
#include <cuda_bf16.h>
#include <math.h>

#define Mm 64
#define Nn 16
#define Dd 300
#define Ff 768
#define VOCAB 100000
#define SURF_L 4
#define CTX_L 50
#define DOC_L 100
#define BODY_L 200
#define HD 60
#define NH 5

#define KD 304               // padded d per tap (300 -> 304)
#define KDP (KD / 2)         // u32 pairs per row = 152

typedef unsigned long long u64;
typedef unsigned int u32;

// ---------------- scratch (__device__ globals, no allocation) ----------------
__device__ float g_Wt_ms[2 * Dd * Ff];     // [k][d][f] for surface conv
__device__ u32 g_WbH[Ff * 5 * KDP];        // [f][tap*152 + dpair] bf16x2 hi
__device__ u32 g_WbL[Ff * 5 * KDP];        // [f][tap*152 + dpair] bf16x2 lo
__device__ float g_ms[Mm * Ff];
__device__ float g_mc[Mm * Ff];
__device__ float g_comb[Nn * 600];
__device__ float g_attscore[Nn];
__device__ float g_local[Mm * Nn];
__device__ float g_tn[Nn];
__device__ float g_cosdt[Nn];

__device__ __forceinline__ int safe_id(const int* p, int i) {
    int v = p[i];
    return v < 0 ? 0 : (v >= VOCAB ? VOCAB - 1 : v);
}

__device__ __forceinline__ u32 smem_to_u32(const void* p) {
    u32 a;
    asm("{ .reg .u64 t; cvta.to.shared.u64 t, %1; cvt.u32.u64 %0, t; }" : "=r"(a) : "l"(p));
    return a;
}
__device__ __forceinline__ void ldsm_x4(u32 addr, u32& r0, u32& r1, u32& r2, u32& r3) {
    asm volatile("ldmatrix.sync.aligned.m8n8.x4.shared.b16 {%0,%1,%2,%3}, [%4];"
                 : "=r"(r0), "=r"(r1), "=r"(r2), "=r"(r3) : "r"(addr));
}
__device__ __forceinline__ void mma_bf16(float* c, u32 a0, u32 a1, u32 a2, u32 a3,
                                         u32 b0, u32 b1) {
    asm volatile(
        "mma.sync.aligned.m16n8k16.row.col.f32.bf16.bf16.f32 "
        "{%0,%1,%2,%3}, {%4,%5,%6,%7}, {%8,%9}, {%0,%1,%2,%3};"
        : "+f"(c[0]), "+f"(c[1]), "+f"(c[2]), "+f"(c[3])
        : "r"(a0), "r"(a1), "r"(a2), "r"(a3), "r"(b0), "r"(b1));
}
__device__ __forceinline__ void split_pair(float a, float b, u32& hi, u32& lo) {
    __nv_bfloat16 ha = __float2bfloat16(a);
    __nv_bfloat16 hb = __float2bfloat16(b);
    __nv_bfloat16 la = __float2bfloat16(a - __bfloat162float(ha));
    __nv_bfloat16 lb = __float2bfloat16(b - __bfloat162float(hb));
    hi = ((u32)__bfloat16_as_ushort(hb) << 16) | (u32)__bfloat16_as_ushort(ha);
    lo = ((u32)__bfloat16_as_ushort(lb) << 16) | (u32)__bfloat16_as_ushort(la);
}

// ---------------- generic helpers ----------------
__device__ __forceinline__ float warp_sum(float v) {
#pragma unroll
    for (int o = 16; o; o >>= 1) v += __shfl_xor_sync(0xFFFFFFFFu, v, o);
    return v;
}
__device__ __forceinline__ float warp_max(float v) {
#pragma unroll
    for (int o = 16; o; o >>= 1) v = fmaxf(v, __shfl_xor_sync(0xFFFFFFFFu, v, o));
    return v;
}
__device__ __forceinline__ float r16_sum(float v) {
#pragma unroll
    for (int o = 8; o; o >>= 1) v += __shfl_xor_sync(0xFFFFu, v, o, 16);
    return v;
}
__device__ __forceinline__ float r16_max(float v) {
#pragma unroll
    for (int o = 8; o; o >>= 1) v = fmaxf(v, __shfl_xor_sync(0xFFFFu, v, o, 16));
    return v;
}
__device__ __forceinline__ float r16_min(float v) {
#pragma unroll
    for (int o = 8; o; o >>= 1) v = fminf(v, __shfl_xor_sync(0xFFFFu, v, o, 16));
    return v;
}

// ---------------- weight prep: Wmc -> bf16 hi/lo [f][tap*152+dp]; Wms transpose ----------------
__global__ void wprep_kernel(const float* __restrict__ Wms,
                             const float* __restrict__ Wmc) {
    int idx = blockIdx.x * blockDim.x + threadIdx.x;
    const int nW = Ff * 5 * KDP;  // 583680
    if (idx < nW) {
        int f = idx / (5 * KDP);
        int r = idx - f * (5 * KDP);
        int tap = r / KDP;
        int dp = r - tap * KDP;
        int d = 2 * dp;
        float a = (d < Dd) ? Wmc[(size_t)f * Dd * 5 + d * 5 + tap] : 0.f;
        float b = (d + 1 < Dd) ? Wmc[(size_t)f * Dd * 5 + (d + 1) * 5 + tap] : 0.f;
        u32 hi, lo;
        split_pair(a, b, hi, lo);
        g_WbH[idx] = hi;
        g_WbL[idx] = lo;
    } else {
        int i = idx - nW;
        if (i < 2 * Dd * Ff) {
            int f = i % Ff;
            int rest = i / Ff;
            int d = rest % Dd;
            int k = rest / Dd;
            g_Wt_ms[i] = Wms[(size_t)f * Dd * 2 + d * 2 + k];
        }
    }
}

// ---------------- surface conv (tiny, scalar float4) ----------------
__launch_bounds__(192)
__global__ void conv_ms_kernel(const int* __restrict__ ids,
                               const float* __restrict__ emb,
                               const float* __restrict__ bias) {
    const int m = blockIdx.x;
    const int tid = threadIdx.x;
    __shared__ float Xs[SURF_L * Dd];
    for (int i = tid; i < SURF_L * Dd; i += 192) {
        int l = i / Dd, d = i - l * Dd;
        Xs[i] = emb[(size_t)safe_id(ids, m * SURF_L + l) * Dd + d];
    }
    __syncthreads();
    float4 acc[3];
#pragma unroll
    for (int t = 0; t < 3; t++) acc[t] = make_float4(0.f, 0.f, 0.f, 0.f);
#pragma unroll
    for (int k = 0; k < 2; k++) {
        const float4* __restrict__ wp = (const float4*)(g_Wt_ms + (size_t)k * Dd * Ff) + tid;
        const float* __restrict__ xk = Xs + k * Dd;
        for (int d = 0; d < Dd; d++) {
            float4 w = wp[(size_t)d * (Ff / 4)];
#pragma unroll
            for (int t = 0; t < 3; t++) {
                float xv = xk[t * Dd + d];
                acc[t].x = fmaf(xv, w.x, acc[t].x);
                acc[t].y = fmaf(xv, w.y, acc[t].y);
                acc[t].z = fmaf(xv, w.z, acc[t].z);
                acc[t].w = fmaf(xv, w.w, acc[t].w);
            }
        }
    }
    float4 b4 = ((const float4*)bias)[tid];
    float4 s = make_float4(0.f, 0.f, 0.f, 0.f);
#pragma unroll
    for (int t = 0; t < 3; t++) {
        s.x += fmaxf(acc[t].x + b4.x, 0.f);
        s.y += fmaxf(acc[t].y + b4.y, 0.f);
        s.z += fmaxf(acc[t].z + b4.z, 0.f);
        s.w += fmaxf(acc[t].w + b4.w, 0.f);
    }
    s.x *= (1.f / 3.f); s.y *= (1.f / 3.f); s.z *= (1.f / 3.f); s.w *= (1.f / 3.f);
    ((float4*)(g_ms + (size_t)m * Ff))[tid] = s;
}

// ---------------- context conv via mma.sync bf16 3-pass GEMM ----------------
// CTA = 2 mentions x 128 f. Warp (mi, nh) computes 48 rows (3 m16) x 64 f (8 n8).
// A = Xs (tap shift = row offset), B = W slab staged per (tap,half) in smem.
#define XHALF 31616              // 52*304*2 bytes per half per mention
#define XMEN (2 * XHALF)         // 63232 per mention (hi+lo)
#define WS_OFF (2 * XMEN)        // 126464
#define SMEM_CONV (WS_OFF + 128 * KD * 2)   // +77824 = 204288

__global__ void __launch_bounds__(128, 1)
conv_mma2_kernel(const int* __restrict__ ids,
                 const float* __restrict__ emb,
                 const float* __restrict__ bias) {
    extern __shared__ char smem[];
    const int tid = threadIdx.x;
    const int lane = tid & 31;
    const int w = tid >> 5;
    const int mi = w >> 1, nh = w & 1;
    const int mp = blockIdx.x;       // mention pair 0..31
    const int f0 = blockIdx.y * 128; // f-range

    // ---- gather + hi/lo split X for both mentions: rows 0..49 real, 50..51 zero
    for (int i = tid; i < 2 * 52 * KDP; i += 128) {
        int m2 = i / (52 * KDP);
        int rem = i - m2 * (52 * KDP);
        int row = rem / KDP;
        int dp = rem - row * KDP;
        int d = 2 * dp;
        float a = 0.f, b = 0.f;
        if (row < CTX_L) {
            const float* er = emb + (size_t)safe_id(ids, (mp * 2 + m2) * CTX_L + row) * Dd;
            if (d < Dd) a = er[d];
            if (d + 1 < Dd) b = er[d + 1];
        }
        u32 hi, lo;
        split_pair(a, b, hi, lo);
        ((u32*)(smem + m2 * XMEN))[row * KDP + dp] = hi;
        ((u32*)(smem + m2 * XMEN + XHALF))[row * KDP + dp] = lo;
    }

    const u32 sb = smem_to_u32(smem);
    const u32 xbase = sb + (u32)(mi * XMEN);
    const u32 wsb = sb + WS_OFF;

    // lane-derived fragment address components (element units)
    const int a_r = lane & 15;
    const int a_k = (lane >> 4) << 3;
    const int b_n = ((lane >> 4) << 3) + (lane & 7);
    const int b_k = ((lane >> 3) & 1) << 3;

    float C[3][8][4];
#pragma unroll
    for (int mt = 0; mt < 3; mt++)
#pragma unroll
        for (int nt = 0; nt < 8; nt++)
#pragma unroll
            for (int j = 0; j < 4; j++) C[mt][nt][j] = 0.f;

    for (int half = 0; half < 2; half++) {
        const u32* __restrict__ wsrc = half ? g_WbL : g_WbH;
        for (int tap = 0; tap < 5; tap++) {
            __syncthreads();  // protect Ws from previous-stage readers (covers X fill too)
            {   // stage W slab [128 f][304 k] for this (tap, half)
                const uint4* __restrict__ src = (const uint4*)wsrc;
                uint4* __restrict__ dst = (uint4*)(smem + WS_OFF);
                for (int i = tid; i < 128 * 38; i += 128) {
                    int fi = i / 38, c = i - fi * 38;
                    dst[i] = src[(size_t)(f0 + fi) * (5 * KDP / 4) + tap * 38 + c];
                }
            }
            __syncthreads();
            for (int ks = 0; ks < 19; ks++) {
                const int k0 = ks * 16;
                u32 Bf[8][2];
#pragma unroll
                for (int p = 0; p < 4; p++) {
                    u32 addr = wsb + (u32)(((nh * 64 + p * 16 + b_n) * KD + k0 + b_k) * 2);
                    ldsm_x4(addr, Bf[2 * p][0], Bf[2 * p][1], Bf[2 * p + 1][0], Bf[2 * p + 1][1]);
                }
#pragma unroll
                for (int mt = 0; mt < 3; mt++) {
                    u32 aoff = (u32)(((mt * 16 + tap + a_r) * KD + k0 + a_k) * 2);
                    u32 A0, A1, A2, A3;
                    ldsm_x4(xbase + aoff, A0, A1, A2, A3);  // X hi
#pragma unroll
                    for (int nt = 0; nt < 8; nt++)
                        mma_bf16(C[mt][nt], A0, A1, A2, A3, Bf[nt][0], Bf[nt][1]);
                    if (half == 0) {
                        ldsm_x4(xbase + XHALF + aoff, A0, A1, A2, A3);  // X lo
#pragma unroll
                        for (int nt = 0; nt < 8; nt++)
                            mma_bf16(C[mt][nt], A0, A1, A2, A3, Bf[nt][0], Bf[nt][1]);
                    }
                }
            }
        }
    }

    // ---- epilogue: stage C, then bias+relu+sum over t
    __syncthreads();
    float* stg = (float*)(smem + WS_OFF);  // [2][48][128]
#pragma unroll
    for (int mt = 0; mt < 3; mt++)
#pragma unroll
        for (int nt = 0; nt < 8; nt++) {
            int row = mt * 16 + (lane >> 2);
            int col = nh * 64 + nt * 8 + (lane & 3) * 2;
            float* base = stg + mi * 6144 + row * 128 + col;
            base[0] = C[mt][nt][0];
            base[1] = C[mt][nt][1];
            base[8 * 128] = C[mt][nt][2];
            base[8 * 128 + 1] = C[mt][nt][3];
        }
    __syncthreads();
    for (int idx = tid; idx < 256; idx += 128) {
        int m2 = idx >> 7, f = idx & 127;
        float b = bias[f0 + f];
        float s = 0.f;
        for (int t = 0; t < 46; t++) s += fmaxf(stg[m2 * 6144 + t * 128 + f] + b, 0.f);
        g_mc[(size_t)(mp * 2 + m2) * Ff + f0 + f] = s * (1.0f / 46.0f);
    }
}

// ---------------- cross attention ----------------
__global__ void attn_kernel(const int* __restrict__ doc_ids,
                            const int* __restrict__ body_ids,
                            const float* __restrict__ emb) {
    const int n = blockIdx.x, h = blockIdx.y, dir = blockIdx.z;
    const int Lq = dir == 0 ? DOC_L : BODY_L;
    const int Lk = dir == 0 ? BODY_L : DOC_L;
    extern __shared__ float sh[];
    float* qs = sh;
    float* ks = qs + Lq * HD;
    float* S = ks + Lk * HD;
    __shared__ float red[60 * 16];

    const int tid = threadIdx.x;  // 256
    const int* qids = dir == 0 ? doc_ids : body_ids + n * BODY_L;
    const int* kids = dir == 0 ? body_ids + n * BODY_L : doc_ids;

    for (int i = tid; i < Lq * HD; i += 256) {
        int l = i / HD, j = i - l * HD;
        qs[i] = emb[(size_t)safe_id(qids, l) * Dd + h * HD + j];
    }
    for (int i = tid; i < Lk * HD; i += 256) {
        int l = i / HD, j = i - l * HD;
        ks[i] = emb[(size_t)safe_id(kids, l) * Dd + h * HD + j];
    }
    __syncthreads();

    const float scale = rsqrtf((float)HD);
    for (int idx = tid; idx < Lq * Lk; idx += 256) {
        int q = idx / Lk, k = idx - q * Lk;
        const float4* qp = (const float4*)(qs + q * HD);
        const float4* kp = (const float4*)(ks + k * HD);
        float s = 0.f;
#pragma unroll
        for (int j = 0; j < HD / 4; j++) {
            float4 qv = qp[j];
            float4 kv = kp[j];
            s = fmaf(qv.x, kv.x, s);
            s = fmaf(qv.y, kv.y, s);
            s = fmaf(qv.z, kv.z, s);
            s = fmaf(qv.w, kv.w, s);
        }
        S[idx] = s * scale;
    }
    __syncthreads();

    const int wid = tid >> 5, lane = tid & 31;
    for (int q = wid; q < Lq; q += 8) {
        float* row = S + q * Lk;
        float mx = -1e30f;
        for (int k = lane; k < Lk; k += 32) mx = fmaxf(mx, row[k]);
        mx = warp_max(mx);
        float sum = 0.f;
        for (int k = lane; k < Lk; k += 32) {
            float e = expf(row[k] - mx);
            row[k] = e;
            sum += e;
        }
        sum = warp_sum(sum);
        float inv = 1.f / sum;
        for (int k = lane; k < Lk; k += 32) row[k] *= inv;
    }
    __syncthreads();

    if (tid < 240) {
        int qg = tid / 15;
        int j4 = tid - qg * 15;
        float4 mx = make_float4(-1e30f, -1e30f, -1e30f, -1e30f);
        for (int q = qg; q < Lq; q += 16) {
            const float* row = S + q * Lk;
            float4 o = make_float4(0.f, 0.f, 0.f, 0.f);
            for (int k = 0; k < Lk; k++) {
                float xv = row[k];
                float4 v = *(const float4*)(ks + k * HD + j4 * 4);
                o.x = fmaf(xv, v.x, o.x);
                o.y = fmaf(xv, v.y, o.y);
                o.z = fmaf(xv, v.z, o.z);
                o.w = fmaf(xv, v.w, o.w);
            }
            mx.x = fmaxf(mx.x, o.x);
            mx.y = fmaxf(mx.y, o.y);
            mx.z = fmaxf(mx.z, o.z);
            mx.w = fmaxf(mx.w, o.w);
        }
        red[(j4 * 4 + 0) * 16 + qg] = mx.x;
        red[(j4 * 4 + 1) * 16 + qg] = mx.y;
        red[(j4 * 4 + 2) * 16 + qg] = mx.z;
        red[(j4 * 4 + 3) * 16 + qg] = mx.w;
    }
    __syncthreads();
    if (tid < 60) {
        float mxv = -1e30f;
#pragma unroll
        for (int g = 0; g < 16; g++) mxv = fmaxf(mxv, red[tid * 16 + g]);
        g_comb[n * 600 + dir * 300 + h * HD + tid] = mxv;
    }
}

// ---------------- attention MLP ----------------
__global__ void attmlp_kernel(const float* __restrict__ W1,
                              const float* __restrict__ b1,
                              const float* __restrict__ W2,
                              const float* __restrict__ b2) {
    const int n = blockIdx.x;
    __shared__ float cb[600];
    __shared__ float partial[10];
    const int tid = threadIdx.x;  // 320
    for (int i = tid; i < 600; i += 320) cb[i] = g_comb[n * 600 + i];
    __syncthreads();
    float v = 0.f;
    if (tid < 300) {
        float a = b1[tid];
        for (int i = 0; i < 600; i++) a = fmaf(cb[i], W1[i * 300 + tid], a);
        a = fmaxf(a, 0.f);
        v = a * W2[tid];
    }
    v = warp_sum(v);
    if ((tid & 31) == 0) partial[tid >> 5] = v;
    __syncthreads();
    if (tid == 0) {
        float s = 0.f;
        for (int w = 0; w < 10; w++) s += partial[w];
        s += b2[0];
        g_attscore[n] = 1.f / (1.f + expf(-s));
    }
}

// ---------------- LocalCtxAttRanker ----------------
__global__ void localctx_kernel(const int* __restrict__ cand_ids,
                                const int* __restrict__ ctx_ids,
                                const float* __restrict__ emb) {
    const int m = blockIdx.x;
    extern __shared__ float sh[];
    float* cs = sh;
    float* xs = cs + Nn * Dd;
    float* tok = xs + CTX_L * Dd;
    float* p = tok + Nn * CTX_L;
    float* ctxv = p + CTX_L;
    const int tid = threadIdx.x;  // 256

    for (int i = tid; i < Nn * Dd; i += 256) {
        int n = i / Dd, d = i - n * Dd;
        cs[i] = emb[(size_t)safe_id(cand_ids, m * Nn + n) * Dd + d];
    }
    for (int i = tid; i < CTX_L * Dd; i += 256) {
        int t = i / Dd, d = i - t * Dd;
        xs[i] = emb[(size_t)safe_id(ctx_ids, m * CTX_L + t) * Dd + d];
    }
    __syncthreads();

    for (int idx = tid; idx < Nn * CTX_L; idx += 256) {
        int n = idx / CTX_L, t = idx - n * CTX_L;
        const float* cp = cs + n * Dd;
        const float* xp = xs + t * Dd;
        float s = 0.f;
        for (int d = 0; d < Dd; d++) s = fmaf(cp[d], xp[d], s);
        tok[idx] = s;
    }
    __syncthreads();
    if (tid < CTX_L) {
        float mx = -1e30f;
        for (int n = 0; n < Nn; n++) mx = fmaxf(mx, tok[n * CTX_L + tid]);
        p[tid] = mx;
    }
    __syncthreads();
    if (tid < 32) {
        float mx = -1e30f;
        for (int t = tid; t < CTX_L; t += 32) mx = fmaxf(mx, p[t]);
        mx = warp_max(mx);
        float sum = 0.f;
        for (int t = tid; t < CTX_L; t += 32) {
            float e = expf(p[t] - mx);
            p[t] = e;
            sum += e;
        }
        sum = warp_sum(sum);
        float inv = 1.f / sum;
        for (int t = tid; t < CTX_L; t += 32) p[t] *= inv;
    }
    __syncthreads();
    for (int d = tid; d < Dd; d += 256) {
        float s = 0.f;
        for (int t = 0; t < CTX_L; t++) s = fmaf(p[t], xs[t * Dd + d], s);
        ctxv[d] = s;
    }
    __syncthreads();
    const int wid = tid >> 5, lane = tid & 31;
    for (int n = wid; n < Nn; n += 8) {
        float s = 0.f;
        for (int d = lane; d < Dd; d += 32) s = fmaf(cs[n * Dd + d], ctxv[d], s);
        s = warp_sum(s);
        if (lane == 0) g_local[m * Nn + n] = s;
    }
}

// ---------------- prep ----------------
__global__ void prep_kernel(const float* __restrict__ title,
                            const float* __restrict__ md) {
    const int w = threadIdx.x >> 5, lane = threadIdx.x & 31;
    float st2 = 0.f, smt = 0.f, sm2 = 0.f;
    for (int j = lane; j < Ff; j += 32) {
        float t = title[w * Ff + j];
        float mv = md[j];
        st2 = fmaf(t, t, st2);
        smt = fmaf(t, mv, smt);
        sm2 = fmaf(mv, mv, sm2);
    }
    st2 = warp_sum(st2);
    smt = warp_sum(smt);
    sm2 = warp_sum(sm2);
    if (lane == 0) {
        float tnv = sqrtf(st2);
        g_tn[w] = tnv;
        g_cosdt[w] = smt / (fmaxf(sqrtf(sm2), 1e-6f) * fmaxf(tnv, 1e-6f));
    }
}

// ---------------- final ----------------
__global__ void final_kernel(const float* __restrict__ title,
                             const float* __restrict__ prior,
                             const float* __restrict__ hand,
                             const float* __restrict__ w7,
                             const float* __restrict__ b7,
                             float* __restrict__ out) {
    const int m = blockIdx.x;
    const int tid = threadIdx.x;  // 256
    const int wid = tid >> 5, lane = tid & 31;
    __shared__ float nms_s, nmc_s;
    __shared__ float dst[Nn], dct[Nn], sc[Nn];

    if (wid == 0) {
        float s = 0.f;
        for (int j = lane; j < Ff; j += 32) {
            float v = g_ms[m * Ff + j];
            s = fmaf(v, v, s);
        }
        s = warp_sum(s);
        if (lane == 0) nms_s = fmaxf(sqrtf(s), 1e-6f);
    }
    if (wid == 1) {
        float s = 0.f;
        for (int j = lane; j < Ff; j += 32) {
            float v = g_mc[m * Ff + j];
            s = fmaf(v, v, s);
        }
        s = warp_sum(s);
        if (lane == 0) nmc_s = fmaxf(sqrtf(s), 1e-6f);
    }
    for (int item = wid; item < 32; item += 8) {
        int n = item & 15;
        int which = item >> 4;
        const float* a = which ? (g_mc + m * Ff) : (g_ms + m * Ff);
        float s = 0.f;
        for (int j = lane; j < Ff; j += 32) s = fmaf(a[j], title[n * Ff + j], s);
        s = warp_sum(s);
        if (lane == 0) {
            if (which) dct[n] = s;
            else dst[n] = s;
        }
    }
    __syncthreads();

    if (tid < Nn) {
        int n = tid;
        float tc = fmaxf(g_tn[n], 1e-6f);
        float cst = dst[n] / (nms_s * tc);
        float cct = dct[n] / (nmc_s * tc);
        float s = b7[0];
        s = fmaf(w7[0], hand[n], s);
        s = fmaf(w7[1], prior[n], s);
        s = fmaf(w7[2], g_local[m * Nn + n], s);
        s = fmaf(w7[3], g_attscore[n], s);
        s = fmaf(w7[4], cst, s);
        s = fmaf(w7[5], g_cosdt[n], s);
        s = fmaf(w7[6], cct, s);
        sc[n] = s;
    }
    __syncthreads();
    if (tid < Nn) {
        float x = sc[tid];
        float mu = r16_sum(x) * (1.f / 16.f);
        float dv = x - mu;
        float var = r16_sum(dv * dv) * (1.f / 15.f);
        float z = dv / sqrtf(var);
        out[m * Nn + tid] = z;
        float zmax = r16_max(z);
        float zmin = r16_min(z);
        float e = expf(z - zmax);
        float es = r16_sum(e);
        out[Mm * Nn + m * Nn + tid] = e / es;
        float u = (z + 1.f - zmin) / (zmax - zmin);
        float us = r16_sum(u);
        out[2 * Mm * Nn + m * Nn + tid] = u / us;
    }
}

// ---------------- launch ----------------
extern "C" void kernel_launch(void* const* d_in, const int* in_sizes, int n_in,
                              void* d_out, int out_size) {
    int e = -1;
    for (int i = 0; i < n_in; i++) {
        if (in_sizes[i] == VOCAB * Dd) { e = i; break; }
    }
    if (e < 0) e = 14;

    const int* mention_vec  = (const int*)d_in[e - 11];
    const int* context_vec  = (const int*)d_in[e - 10];
    const int* doc_vec      = (const int*)d_in[e - 9];
    const float* title      = (const float*)d_in[e - 8];
    const int* body_vec     = (const int*)d_in[e - 7];
    const float* prior      = (const float*)d_in[e - 5];
    const int* men2cands    = (const int*)d_in[e - 4];
    const int* contexts_ids = (const int*)d_in[e - 3];
    const float* hand       = (const float*)d_in[e - 2];
    const float* bert       = (const float*)d_in[e - 1];
    const float* emb        = (const float*)d_in[e];
    const float* Wms        = (const float*)d_in[e + 1];
    const float* bms        = (const float*)d_in[e + 2];
    const float* Wmc        = (const float*)d_in[e + 3];
    const float* bmc        = (const float*)d_in[e + 4];
    const float* w7         = (const float*)d_in[e + 5];
    const float* b7         = (const float*)d_in[e + 6];
    const float* W1         = (const float*)d_in[e + 7];
    const float* b1         = (const float*)d_in[e + 8];
    const float* W2         = (const float*)d_in[e + 9];
    const float* b2         = (const float*)d_in[e + 10];
    float* out = (float*)d_out;

    static bool s_init = false;
    static cudaStream_t s0, s1, s2;
    static cudaEvent_t evF, ev0, ev1, ev2;
    if (!s_init) {
        cudaStreamCreateWithFlags(&s0, cudaStreamNonBlocking);
        cudaStreamCreateWithFlags(&s1, cudaStreamNonBlocking);
        cudaStreamCreateWithFlags(&s2, cudaStreamNonBlocking);
        cudaEventCreateWithFlags(&evF, cudaEventDisableTiming);
        cudaEventCreateWithFlags(&ev0, cudaEventDisableTiming);
        cudaEventCreateWithFlags(&ev1, cudaEventDisableTiming);
        cudaEventCreateWithFlags(&ev2, cudaEventDisableTiming);
        s_init = true;
    }

    cudaFuncSetAttribute(attn_kernel, cudaFuncAttributeMaxDynamicSharedMemorySize, 152000);
    cudaFuncSetAttribute(localctx_kernel, cudaFuncAttributeMaxDynamicSharedMemorySize, 84000);
    cudaFuncSetAttribute(conv_mma2_kernel, cudaFuncAttributeMaxDynamicSharedMemorySize, SMEM_CONV);

    // fork from incoming stream
    cudaEventRecord(evF, 0);
    cudaStreamWaitEvent(s0, evF, 0);
    cudaStreamWaitEvent(s1, evF, 0);
    cudaStreamWaitEvent(s2, evF, 0);

    // s0: weight prep -> convs (critical path)
    wprep_kernel<<<(Ff * 5 * KDP + 2 * Dd * Ff + 255) / 256, 256, 0, s0>>>(Wms, Wmc);
    conv_ms_kernel<<<Mm, 192, 0, s0>>>(mention_vec, emb, bms);
    conv_mma2_kernel<<<dim3(Mm / 2, Ff / 128), 128, SMEM_CONV, s0>>>(context_vec, emb, bmc);
    cudaEventRecord(ev0, s0);

    // s1: cross attention + MLP score
    attn_kernel<<<dim3(Nn, NH, 2), 256, 152000, s1>>>(doc_vec, body_vec, emb);
    attmlp_kernel<<<Nn, 320, 0, s1>>>(W1, b1, W2, b2);
    cudaEventRecord(ev1, s1);

    // s2: local context ranker + title prep
    localctx_kernel<<<Mm, 256, 84000, s2>>>(men2cands, contexts_ids, emb);
    prep_kernel<<<1, 512, 0, s2>>>(title, bert);
    cudaEventRecord(ev2, s2);

    // join on incoming stream
    cudaStreamWaitEvent(0, ev0, 0);
    cudaStreamWaitEvent(0, ev1, 0);
    cudaStreamWaitEvent(0, ev2, 0);

    // final score + normalizations
    final_kernel<<<Mm, 256>>>(title, prior, hand, w7, b7, out);
}